// round 15
// baseline (speedup 1.0000x reference)
#include <cuda_runtime.h>
#include <cuda_bf16.h>
#include <cstdint>

#define NN   50000
#define NE   640000
#define EPSV 1e-5f

// ---------------- scratch (device globals; no allocation at launch) ----------------
__device__ __align__(128) __nv_bfloat16 g_xh[(size_t)NE * 128];  // BN1 input (bias added), bf16
__device__ __align__(128) float g_y[(size_t)NN * 128];     // BN2 input
__device__ __align__(128) float g_agg[(size_t)NN * 128];   // scatter-sum target
__device__ __align__(128) float g_P[(size_t)NN * 128];     // h @ W1a
__device__ __align__(128) float g_Q[(size_t)NN * 128];     // h @ W1b
__device__ __align__(128) float g_s1[128], g_q1[128], g_s2[128], g_q2[128];
// transposed + hi/lo-split weights ([N, K] K-contiguous)
__device__ __align__(128) __nv_bfloat16 g_Wa_hi[128 * 128],  g_Wa_lo[128 * 128];
__device__ __align__(128) __nv_bfloat16 g_Wb_hi[128 * 128],  g_Wb_lo[128 * 128];
__device__ __align__(128) __nv_bfloat16 g_Wc_hi[128 * 64],   g_Wc_lo[128 * 64];
__device__ __align__(128) __nv_bfloat16 g_W2t_hi[128 * 128], g_W2t_lo[128 * 128];
__device__ __align__(128) __nv_bfloat16 g_W3t_hi[128 * 256], g_W3t_lo[128 * 256];
__device__ __align__(128) __nv_bfloat16 g_W4t_hi[128 * 128], g_W4t_lo[128 * 128];

// ---------------- small helpers ----------------
__device__ __forceinline__ uint32_t smem_u32(const void* p) {
    return (uint32_t)__cvta_generic_to_shared(p);
}
__device__ __forceinline__ uint32_t swz(uint32_t o) { return o ^ ((o >> 3) & 0x70); }
__device__ __forceinline__ void sts64(uint32_t a, uint32_t x, uint32_t y) {
    asm volatile("st.shared.v2.b32 [%0], {%1,%2};" :: "r"(a), "r"(x), "r"(y));
}
__device__ __forceinline__ void sts128(uint32_t a, uint4 v) {
    asm volatile("st.shared.v4.b32 [%0], {%1,%2,%3,%4};" :: "r"(a), "r"(v.x), "r"(v.y), "r"(v.z), "r"(v.w));
}
__device__ __forceinline__ void sts64f(uint32_t a, float x, float y) {
    asm volatile("st.shared.v2.f32 [%0], {%1,%2};" :: "r"(a), "f"(x), "f"(y));
}
__device__ __forceinline__ float lds32(uint32_t a) {
    float v; asm volatile("ld.shared.f32 %0, [%1];" : "=f"(v) : "r"(a)); return v;
}
__device__ __forceinline__ float4 lds128(uint32_t a) {
    float4 v;
    asm volatile("ld.shared.v4.f32 {%0,%1,%2,%3}, [%4];"
                 : "=f"(v.x), "=f"(v.y), "=f"(v.z), "=f"(v.w) : "r"(a));
    return v;
}
__device__ __forceinline__ uint4 lds128u(uint32_t a) {
    uint4 v;
    asm volatile("ld.shared.v4.b32 {%0,%1,%2,%3}, [%4];"
                 : "=r"(v.x), "=r"(v.y), "=r"(v.z), "=r"(v.w) : "r"(a));
    return v;
}
__device__ __forceinline__ void cpasync16(uint32_t dst, const void* src) {
    asm volatile("cp.async.ca.shared.global [%0], [%1], 16;" :: "r"(dst), "l"(src));
}
__device__ __forceinline__ uint32_t pkbf(__nv_bfloat16 a, __nv_bfloat16 b) {
    __nv_bfloat162 t(a, b);
    return *reinterpret_cast<uint32_t*>(&t);
}
__device__ __forceinline__ void split2(float a, float b, uint32_t& hh, uint32_t& ll) {
    __nv_bfloat16 ha = __float2bfloat16_rn(a), hb = __float2bfloat16_rn(b);
    float la = a - __bfloat162float(ha), lb = b - __bfloat162float(hb);
    hh = pkbf(ha, hb);
    ll = pkbf(__float2bfloat16_rn(la), __float2bfloat16_rn(lb));
}
__device__ __forceinline__ void red4(float* p, float a, float b, float c, float d) {
    asm volatile("red.global.add.v4.f32 [%0], {%1, %2, %3, %4};"
                 :: "l"(p), "f"(a), "f"(b), "f"(c), "f"(d) : "memory");
}

// ---------------- tensor-core primitives ----------------
__device__ __forceinline__ void mma16816(float* c, const uint32_t* a, uint32_t b0, uint32_t b1) {
    asm volatile("mma.sync.aligned.m16n8k16.row.col.f32.bf16.bf16.f32 "
        "{%0,%1,%2,%3}, {%4,%5,%6,%7}, {%8,%9}, {%0,%1,%2,%3};"
        : "+f"(c[0]), "+f"(c[1]), "+f"(c[2]), "+f"(c[3])
        : "r"(a[0]), "r"(a[1]), "r"(a[2]), "r"(a[3]), "r"(b0), "r"(b1));
}
__device__ __forceinline__ void ldsm4(uint32_t* r, uint32_t addr) {
    asm volatile("ldmatrix.sync.aligned.m8n8.x4.shared.b16 {%0,%1,%2,%3}, [%4];"
        : "=r"(r[0]), "=r"(r[1]), "=r"(r[2]), "=r"(r[3]) : "r"(addr));
}

// One 64-deep K chunk: 4 k16-steps, warp tile 32(M)x64(N), 3-term hi/lo split.
__device__ __forceinline__ void mma_chunk(
    uint32_t AH, uint32_t AL, uint32_t BH, uint32_t BL,
    uint32_t rowApart, uint32_t kA, uint32_t maskA,
    uint32_t rowBpart, uint32_t kB, uint32_t maskB,
    float (&acc)[2][4][2][4])
{
#pragma unroll
    for (int s = 0; s < 4; ++s) {
        const uint32_t offA = (kA + s * 32) ^ maskA;
        const uint32_t offB = (kB + s * 32) ^ maskB;
        uint32_t ah[2][4], al[2][4];
#pragma unroll
        for (int i = 0; i < 2; ++i) {
            ldsm4(ah[i], AH + rowApart + i * 2048 + offA);
            ldsm4(al[i], AL + rowApart + i * 2048 + offA);
        }
#pragma unroll
        for (int j = 0; j < 4; ++j) {
            uint32_t bh[4], bl[4];
            ldsm4(bh, BH + rowBpart + j * 2048 + offB);
            ldsm4(bl, BL + rowBpart + j * 2048 + offB);
#pragma unroll
            for (int i = 0; i < 2; ++i) {
#pragma unroll
                for (int hh = 0; hh < 2; ++hh) {
                    mma16816(acc[i][j][hh], ah[i], bh[hh * 2], bh[hh * 2 + 1]);
                    mma16816(acc[i][j][hh], ah[i], bl[hh * 2], bl[hh * 2 + 1]);
                    mma16816(acc[i][j][hh], al[i], bh[hh * 2], bh[hh * 2 + 1]);
                }
            }
        }
    }
}

#define SS 132
#define DSMEM_BYTES (1024 + 128 * SS * 4)                 // 4-tile kernels with stage
#define DSMEM_GEMM2 (1024 + 4 * 16384 + 128 * 144)        // + 18KB chunk-1 prefetch buffer

// warp/lane geometry + accumulator init
#define TC_GEOM()                                                                  \
    const int w = t >> 5, l = t & 31;                                              \
    const int mw = (w >> 1) * 32, nw = (w & 1) * 64;                               \
    const uint32_t rowApart = (uint32_t)(mw + (l & 15)) * 128;                     \
    const uint32_t kA = (uint32_t)(l >> 4) * 16;                                   \
    const uint32_t maskA = (uint32_t)(l & 7) << 4;                                 \
    const uint32_t rowBpart = (uint32_t)(nw + (l & 7) + ((l >> 4) << 3)) * 128;    \
    const uint32_t kB = (uint32_t)((l >> 3) & 1) * 16;                             \
    const uint32_t maskB = maskA;                                                  \
    float acc[2][4][2][4];                                                         \
    _Pragma("unroll") for (int i = 0; i < 2; ++i)                                  \
    _Pragma("unroll") for (int j = 0; j < 4; ++j)                                  \
    _Pragma("unroll") for (int hh = 0; hh < 2; ++hh)                               \
    _Pragma("unroll") for (int q = 0; q < 4; ++q) acc[i][j][hh][q] = 0.f;

#define TC_TILES()                                                                 \
    const uint32_t base = (smem_u32(dsm) + 1023) & ~1023u;                         \
    const uint32_t AH = base, AL = base + 16384, BH = base + 32768, BL = base + 49152;

#define TC_STAGE()                                                                 \
    _Pragma("unroll") for (int i = 0; i < 2; ++i)                                  \
    _Pragma("unroll") for (int j = 0; j < 4; ++j)                                  \
    _Pragma("unroll") for (int hh = 0; hh < 2; ++hh) {                             \
        const int col  = nw + j * 16 + hh * 8 + 2 * (l & 3);                       \
        const int row0 = mw + i * 16 + (l >> 2);                                   \
        sts64f(base + (uint32_t)(row0 * SS + col) * 4,       acc[i][j][hh][0], acc[i][j][hh][1]); \
        sts64f(base + (uint32_t)((row0 + 8) * SS + col) * 4, acc[i][j][hh][2], acc[i][j][hh][3]); \
    }

// ---------------- kernel: transpose + hi/lo split all weights ; zero stat vectors ----------------
__global__ void k_prep(const float* __restrict__ W1, const float* __restrict__ W2,
                       const float* __restrict__ W3, const float* __restrict__ W4) {
    const int stride = gridDim.x * blockDim.x;
    const int t0 = blockIdx.x * blockDim.x + threadIdx.x;
    if (blockIdx.x == 0 && threadIdx.x < 128) {
        g_s1[threadIdx.x] = 0.f; g_q1[threadIdx.x] = 0.f;
        g_s2[threadIdx.x] = 0.f; g_q2[threadIdx.x] = 0.f;
    }
    for (int idx = t0; idx < 128 * 128; idx += stride) {
        const int n = idx >> 7, k = idx & 127;
        float v = W1[k * 128 + n];
        __nv_bfloat16 hv = __float2bfloat16_rn(v);
        g_Wa_hi[idx] = hv; g_Wa_lo[idx] = __float2bfloat16_rn(v - __bfloat162float(hv));
        v = W1[(128 + k) * 128 + n];
        hv = __float2bfloat16_rn(v);
        g_Wb_hi[idx] = hv; g_Wb_lo[idx] = __float2bfloat16_rn(v - __bfloat162float(hv));
        v = W2[k * 128 + n];
        hv = __float2bfloat16_rn(v);
        g_W2t_hi[idx] = hv; g_W2t_lo[idx] = __float2bfloat16_rn(v - __bfloat162float(hv));
        v = W4[k * 128 + n];
        hv = __float2bfloat16_rn(v);
        g_W4t_hi[idx] = hv; g_W4t_lo[idx] = __float2bfloat16_rn(v - __bfloat162float(hv));
    }
    for (int idx = t0; idx < 128 * 64; idx += stride) {
        const int n = idx >> 6, k = idx & 63;
        const float v = W1[(256 + k) * 128 + n];
        const __nv_bfloat16 hv = __float2bfloat16_rn(v);
        g_Wc_hi[idx] = hv; g_Wc_lo[idx] = __float2bfloat16_rn(v - __bfloat162float(hv));
    }
    for (int idx = t0; idx < 128 * 256; idx += stride) {
        const int n = idx >> 8, k = idx & 255;
        const float v = W3[k * 128 + n];
        const __nv_bfloat16 hv = __float2bfloat16_rn(v);
        g_W3t_hi[idx] = hv; g_W3t_lo[idx] = __float2bfloat16_rn(v - __bfloat162float(hv));
    }
}

// ---------------- k_pq: P = h @ W1a, Q = h @ W1b ; sel==1 also zeros g_agg rows ----------------
__global__ __launch_bounds__(256, 2) void k_pq(const float* __restrict__ h) {
    extern __shared__ __align__(16) char dsm[];
    const int t = threadIdx.x;
    const int r0 = blockIdx.x * 128;
    const int sel = blockIdx.y;

    // zero this block's g_agg rows early (independent of the GEMM)
    if (sel == 1) {
        const int zr = r0 + (t >> 1);
        if (zr < NN) {
            float4* za = (float4*)&g_agg[(size_t)zr * 128 + (t & 1) * 64];
            const float4 z = make_float4(0.f, 0.f, 0.f, 0.f);
#pragma unroll
            for (int q = 0; q < 16; ++q) za[q] = z;
        }
    }

    TC_TILES();
    TC_GEOM();

    const __nv_bfloat16* WH = sel ? g_Wb_hi : g_Wa_hi;
    const __nv_bfloat16* WL = sel ? g_Wb_lo : g_Wa_lo;

    const int row = t >> 1, c0 = (t & 1) * 32;
    int rg = r0 + row; if (rg >= NN) rg = NN - 1;

    for (int kc = 0; kc < 2; ++kc) {
        __syncthreads();
        const float* ap = h + (size_t)rg * 128 + kc * 64 + c0;
#pragma unroll
        for (int j = 0; j < 8; ++j) {
            const float4 f = *(const float4*)(ap + 4 * j);
            uint32_t h01, l01, h23, l23;
            split2(f.x, f.y, h01, l01);
            split2(f.z, f.w, h23, l23);
            const uint32_t sw = swz((uint32_t)(row * 128 + (c0 + 4 * j) * 2));
            sts64(AH + sw, h01, h23);
            sts64(AL + sw, l01, l23);
        }
        const __nv_bfloat16* ph = WH + row * 128 + kc * 64 + c0;
        const __nv_bfloat16* pl = WL + row * 128 + kc * 64 + c0;
#pragma unroll
        for (int j = 0; j < 4; ++j) {
            const uint4 vh = *(const uint4*)(ph + 8 * j);
            const uint4 vl = *(const uint4*)(pl + 8 * j);
            const uint32_t sw = swz((uint32_t)(row * 128 + (c0 + 8 * j) * 2));
            sts128(BH + sw, vh);
            sts128(BL + sw, vl);
        }
        __syncthreads();
        mma_chunk(AH, AL, BH, BL, rowApart, kA, maskA, rowBpart, kB, maskB, acc);
    }
    __syncthreads();
    TC_STAGE();
    __syncthreads();

    const int r = t >> 1, ch = (t & 1) * 64;
    const int orow = r0 + r;
    if (orow < NN) {
        float* po = (sel ? g_Q : g_P) + (size_t)orow * 128 + ch;
#pragma unroll
        for (int q = 0; q < 16; ++q)
            *(float4*)(po + 4 * q) = lds128(base + (uint32_t)(r * SS + ch + 4 * q) * 4);
    }
}

// ---------------- k_edge1: x = ea@Wc + P[src] + Q[dst] + b1 -> g_xh(bf16) ; fused stats ----------------
__global__ __launch_bounds__(256, 2) void k_edge1(
    const float* __restrict__ ea, const float* __restrict__ b1,
    const int* __restrict__ src, const int* __restrict__ dst)
{
    extern __shared__ __align__(16) char dsm[];
    __shared__ int sSoff[128], sDoff[128];
    __shared__ float sB[128], sS[128], sQs[128];

    const int t = threadIdx.x;
    const int e0 = blockIdx.x * 128;

    TC_TILES();
    TC_GEOM();

    if (t < 128) { sSoff[t] = src[e0 + t] * 128; sB[t] = b1[t]; sS[t] = 0.f; sQs[t] = 0.f; }
    else         sDoff[t - 128] = dst[e0 + t - 128] * 128;

    const int row = t >> 1, c0 = (t & 1) * 32;

    // single K=64 chunk: A = ea rows, B = W1c
    {
        const float* ap = ea + (size_t)(e0 + row) * 64 + c0;
#pragma unroll
        for (int j = 0; j < 4; ++j) {
            const float4 f0 = *(const float4*)(ap + 8 * j);
            const float4 f1 = *(const float4*)(ap + 8 * j + 4);
            uint32_t hv0, lv0, hv1, lv1, hv2, lv2, hv3, lv3;
            split2(f0.x, f0.y, hv0, lv0);
            split2(f0.z, f0.w, hv1, lv1);
            split2(f1.x, f1.y, hv2, lv2);
            split2(f1.z, f1.w, hv3, lv3);
            const uint32_t sw = swz((uint32_t)(row * 128 + (c0 + 8 * j) * 2));
            sts128(AH + sw, make_uint4(hv0, hv1, hv2, hv3));
            sts128(AL + sw, make_uint4(lv0, lv1, lv2, lv3));
        }
        const __nv_bfloat16* ph = g_Wc_hi + row * 64 + c0;
        const __nv_bfloat16* pl = g_Wc_lo + row * 64 + c0;
#pragma unroll
        for (int j = 0; j < 4; ++j) {
            const uint4 vh = *(const uint4*)(ph + 8 * j);
            const uint4 vl = *(const uint4*)(pl + 8 * j);
            const uint32_t sw = swz((uint32_t)(row * 128 + (c0 + 8 * j) * 2));
            sts128(BH + sw, vh);
            sts128(BL + sw, vl);
        }
        __syncthreads();
        mma_chunk(AH, AL, BH, BL, rowApart, kA, maskA, rowBpart, kB, maskB, acc);
    }
    __syncthreads();
    TC_STAGE();
    __syncthreads();

    // gather P/Q + bias; write g_xh (bf16); accumulate column stats in registers
    float sacc[16], qacc[16];
#pragma unroll
    for (int i = 0; i < 16; ++i) { sacc[i] = 0.f; qacc[i] = 0.f; }

#pragma unroll
    for (int pass = 0; pass < 4; ++pass) {
        const int r = pass * 32 + (t >> 3);
        const float* pP = g_P + sSoff[r];
        const float* pQ = g_Q + sDoff[r];
        __nv_bfloat16* gx = g_xh + (size_t)(e0 + r) * 128;
#pragma unroll
        for (int q = 0; q < 4; ++q) {
            const int col = (t & 7) * 4 + 32 * q;
            float4 v = lds128(base + (uint32_t)(r * SS + col) * 4);
            const float4 p4 = *(const float4*)(pP + col);
            const float4 q4 = *(const float4*)(pQ + col);
            v.x += p4.x + q4.x + sB[col];
            v.y += p4.y + q4.y + sB[col + 1];
            v.z += p4.z + q4.z + sB[col + 2];
            v.w += p4.w + q4.w + sB[col + 3];
            uint2 pk;
            pk.x = pkbf(__float2bfloat16_rn(v.x), __float2bfloat16_rn(v.y));
            pk.y = pkbf(__float2bfloat16_rn(v.z), __float2bfloat16_rn(v.w));
            *(uint2*)(gx + col) = pk;
            sacc[q * 4 + 0] += v.x; qacc[q * 4 + 0] += v.x * v.x;
            sacc[q * 4 + 1] += v.y; qacc[q * 4 + 1] += v.y * v.y;
            sacc[q * 4 + 2] += v.z; qacc[q * 4 + 2] += v.z * v.z;
            sacc[q * 4 + 3] += v.w; qacc[q * 4 + 3] += v.w * v.w;
        }
    }
    // reduce across lanes sharing the same column set (lane, lane^8, lane^16, lane^24)
#pragma unroll
    for (int i = 0; i < 16; ++i) {
        sacc[i] += __shfl_xor_sync(0xffffffffu, sacc[i], 8);
        sacc[i] += __shfl_xor_sync(0xffffffffu, sacc[i], 16);
        qacc[i] += __shfl_xor_sync(0xffffffffu, qacc[i], 8);
        qacc[i] += __shfl_xor_sync(0xffffffffu, qacc[i], 16);
    }
    if ((t & 31) < 8) {
#pragma unroll
        for (int q = 0; q < 4; ++q)
#pragma unroll
            for (int e = 0; e < 4; ++e) {
                const int c = (t & 7) * 4 + e + 32 * q;
                atomicAdd(&sS[c],  sacc[q * 4 + e]);
                atomicAdd(&sQs[c], qacc[q * 4 + e]);
            }
    }
    __syncthreads();
    if (t < 128) {
        atomicAdd(&g_s1[t], sS[t]);
        atomicAdd(&g_q1[t], sQs[t]);
    }
}

// ---------------- k_gemm2: messages = relu(BN(g_xh)) @ W2 + b2 ; scatter-add ----------------
__global__ __launch_bounds__(256, 2) void k_gemm2_tc(
    const float* __restrict__ b2, const int* __restrict__ dst,
    const float* __restrict__ g1, const float* __restrict__ be1)
{
    extern __shared__ __align__(16) char dsm[];
    __shared__ int sDoff[128];
    __shared__ float sB[128], sA[128], sC[128];

    const int t = threadIdx.x;
    const int e0 = blockIdx.x * 128;

    TC_TILES();
    const uint32_t Xb = base + 65536;   // 128 rows x 144B prefetch buffer for chunk 1
    TC_GEOM();

    const int row = t >> 1, c0 = (t & 1) * 32;

    // prefetch chunk-1 A data (bf16, 64B per thread) while chunk 0 runs
    {
        const char* srcp = (const char*)(g_xh + (size_t)(e0 + row) * 128 + 64) + (t & 1) * 64;
        const uint32_t dstp = Xb + (uint32_t)row * 144 + (t & 1) * 64;
#pragma unroll
        for (int j = 0; j < 4; ++j) cpasync16(dstp + 16 * j, srcp + 16 * j);
        asm volatile("cp.async.commit_group;");
    }

    if (t < 128) {
        sDoff[t] = dst[e0 + t] * 128;
        sB[t] = b2[t];
        // inline BN1 fold (identical across blocks, deterministic)
        const float m   = g_s1[t] * (1.0f / (float)NE);
        const float var = fmaf(-m, m, g_q1[t] * (1.0f / (float)NE));
        const float a   = g1[t] * rsqrtf(fmaxf(var, 0.f) + EPSV);
        sA[t] = a;
        sC[t] = fmaf(-m, a, be1[t]);
    }

    for (int kc = 0; kc < 2; ++kc) {
        __syncthreads();
        if (kc == 1) asm volatile("cp.async.wait_group 0;" ::: "memory");
#pragma unroll
        for (int j = 0; j < 4; ++j) {
            uint4 u;
            if (kc == 0) u = *(const uint4*)(g_xh + (size_t)(e0 + row) * 128 + c0 + 8 * j);
            else         u = lds128u(Xb + (uint32_t)row * 144 + (c0 + 8 * j) * 2);
            const int cc = kc * 64 + c0 + 8 * j;
            uint32_t hv[4], lv[4];
            {
                const float2 f = __bfloat1622float2(*reinterpret_cast<__nv_bfloat162*>(&u.x));
                const float r0 = fmaxf(fmaf(sA[cc],     f.x, sC[cc]),     0.f);
                const float r1 = fmaxf(fmaf(sA[cc + 1], f.y, sC[cc + 1]), 0.f);
                split2(r0, r1, hv[0], lv[0]);
            }
            {
                const float2 f = __bfloat1622float2(*reinterpret_cast<__nv_bfloat162*>(&u.y));
                const float r0 = fmaxf(fmaf(sA[cc + 2], f.x, sC[cc + 2]), 0.f);
                const float r1 = fmaxf(fmaf(sA[cc + 3], f.y, sC[cc + 3]), 0.f);
                split2(r0, r1, hv[1], lv[1]);
            }
            {
                const float2 f = __bfloat1622float2(*reinterpret_cast<__nv_bfloat162*>(&u.z));
                const float r0 = fmaxf(fmaf(sA[cc + 4], f.x, sC[cc + 4]), 0.f);
                const float r1 = fmaxf(fmaf(sA[cc + 5], f.y, sC[cc + 5]), 0.f);
                split2(r0, r1, hv[2], lv[2]);
            }
            {
                const float2 f = __bfloat1622float2(*reinterpret_cast<__nv_bfloat162*>(&u.w));
                const float r0 = fmaxf(fmaf(sA[cc + 6], f.x, sC[cc + 6]), 0.f);
                const float r1 = fmaxf(fmaf(sA[cc + 7], f.y, sC[cc + 7]), 0.f);
                split2(r0, r1, hv[3], lv[3]);
            }
            const uint32_t sw = swz((uint32_t)(row * 128 + (c0 + 8 * j) * 2));
            sts128(AH + sw, make_uint4(hv[0], hv[1], hv[2], hv[3]));
            sts128(AL + sw, make_uint4(lv[0], lv[1], lv[2], lv[3]));
        }
        const __nv_bfloat16* ph = g_W2t_hi + row * 128 + kc * 64 + c0;
        const __nv_bfloat16* pl = g_W2t_lo + row * 128 + kc * 64 + c0;
#pragma unroll
        for (int j = 0; j < 4; ++j) {
            const uint4 vh = *(const uint4*)(ph + 8 * j);
            const uint4 vl = *(const uint4*)(pl + 8 * j);
            const uint32_t sw = swz((uint32_t)(row * 128 + (c0 + 8 * j) * 2));
            sts128(BH + sw, vh);
            sts128(BL + sw, vl);
        }
        __syncthreads();
        mma_chunk(AH, AL, BH, BL, rowApart, kA, maskA, rowBpart, kB, maskB, acc);
    }
    __syncthreads();
    TC_STAGE();
    __syncthreads();

    const int r = t >> 1, ch = (t & 1) * 64;
    float* ga = &g_agg[(size_t)sDoff[r] + ch];
#pragma unroll
    for (int q = 0; q < 16; ++q) {
        float4 v = lds128(base + (uint32_t)(r * SS + ch + 4 * q) * 4);
        red4(ga + 4 * q,
             v.x + sB[ch + 4 * q],     v.y + sB[ch + 4 * q + 1],
             v.z + sB[ch + 4 * q + 2], v.w + sB[ch + 4 * q + 3]);
    }
}

// ---------------- k_gemm3: y = [h|agg] @ W3 + b3 ; column stats ----------------
__global__ __launch_bounds__(256, 2) void k_gemm3_tc(
    const float* __restrict__ h, const float* __restrict__ b3)
{
    extern __shared__ __align__(16) char dsm[];
    __shared__ float sB[128];

    const int t = threadIdx.x;
    const int r0 = blockIdx.x * 128;

    TC_TILES();
    TC_GEOM();

    if (t < 128) sB[t] = b3[t];

    const int row = t >> 1, c0 = (t & 1) * 32;
    int rg = r0 + row; if (rg >= NN) rg = NN - 1;

    for (int kc = 0; kc < 4; ++kc) {
        __syncthreads();
        const int kg = kc * 64 + c0;
        const float* ap = (kg < 128) ? (h + (size_t)rg * 128 + kg)
                                     : (&g_agg[(size_t)rg * 128 + (kg - 128)]);
#pragma unroll
        for (int j = 0; j < 8; ++j) {
            const float4 f = *(const float4*)(ap + 4 * j);
            uint32_t h01, l01, h23, l23;
            split2(f.x, f.y, h01, l01);
            split2(f.z, f.w, h23, l23);
            const uint32_t sw = swz((uint32_t)(row * 128 + (c0 + 4 * j) * 2));
            sts64(AH + sw, h01, h23);
            sts64(AL + sw, l01, l23);
        }
        const __nv_bfloat16* ph = g_W3t_hi + row * 256 + kc * 64 + c0;
        const __nv_bfloat16* pl = g_W3t_lo + row * 256 + kc * 64 + c0;
#pragma unroll
        for (int j = 0; j < 4; ++j) {
            const uint4 vh = *(const uint4*)(ph + 8 * j);
            const uint4 vl = *(const uint4*)(pl + 8 * j);
            const uint32_t sw = swz((uint32_t)(row * 128 + (c0 + 8 * j) * 2));
            sts128(BH + sw, vh);
            sts128(BL + sw, vl);
        }
        __syncthreads();
        mma_chunk(AH, AL, BH, BL, rowApart, kA, maskA, rowBpart, kB, maskB, acc);
    }
    __syncthreads();
    TC_STAGE();
    __syncthreads();

    const int r = t >> 1, ch = (t & 1) * 64;
    const int orow = r0 + r;
    if (orow < NN) {
        float* gy = &g_y[(size_t)orow * 128 + ch];
#pragma unroll
        for (int q = 0; q < 16; ++q) {
            float4 v = lds128(base + (uint32_t)(r * SS + ch + 4 * q) * 4);
            v.x += sB[ch + 4 * q];
            v.y += sB[ch + 4 * q + 1];
            v.z += sB[ch + 4 * q + 2];
            v.w += sB[ch + 4 * q + 3];
            *(float4*)(gy + 4 * q) = v;
        }
    }
    {
        int lim = NN - r0; if (lim > 128) lim = 128;
        const int col = t & 127, half = t >> 7;
        const float bias = sB[col];
        float s = 0.f, q = 0.f;
        const int rend = min(half * 64 + 64, lim);
        for (int rr = half * 64; rr < rend; ++rr) {
            const float v = lds32(base + (uint32_t)(rr * SS + col) * 4) + bias;
            s += v; q += v * v;
        }
        atomicAdd(&g_s2[col], s);
        atomicAdd(&g_q2[col], q);
    }
}

// ---------------- k_final: h_new = relu(BN(y)) @ W4 + b4 ; residual + LayerNorm ----------------
__global__ __launch_bounds__(256, 2) void k_final_tc(
    const float* __restrict__ h, const float* __restrict__ b4,
    const float* __restrict__ lng, const float* __restrict__ lnb,
    const float* __restrict__ g2, const float* __restrict__ be2,
    float* __restrict__ out)
{
    extern __shared__ __align__(16) char dsm[];
    __shared__ float sB[128], sA[128], sC[128], sG[128], sLb[128];

    const int t = threadIdx.x;
    const int r0 = blockIdx.x * 128;

    TC_TILES();
    TC_GEOM();

    if (t < 128) {
        sB[t] = b4[t];
        sG[t] = lng[t]; sLb[t] = lnb[t];
        // inline BN2 fold
        const float m   = g_s2[t] * (1.0f / (float)NN);
        const float var = fmaf(-m, m, g_q2[t] * (1.0f / (float)NN));
        const float a   = g2[t] * rsqrtf(fmaxf(var, 0.f) + EPSV);
        sA[t] = a;
        sC[t] = fmaf(-m, a, be2[t]);
    }

    const int row = t >> 1, c0 = (t & 1) * 32;
    int rg = r0 + row; if (rg >= NN) rg = NN - 1;

    for (int kc = 0; kc < 2; ++kc) {
        __syncthreads();
        const float* ap = g_y + (size_t)rg * 128 + kc * 64 + c0;
#pragma unroll
        for (int j = 0; j < 8; ++j) {
            const float4 f = *(const float4*)(ap + 4 * j);
            const int col = kc * 64 + c0 + 4 * j;
            const float x0 = fmaxf(fmaf(sA[col],     f.x, sC[col]),     0.f);
            const float x1 = fmaxf(fmaf(sA[col + 1], f.y, sC[col + 1]), 0.f);
            const float x2 = fmaxf(fmaf(sA[col + 2], f.z, sC[col + 2]), 0.f);
            const float x3 = fmaxf(fmaf(sA[col + 3], f.w, sC[col + 3]), 0.f);
            uint32_t h01, l01, h23, l23;
            split2(x0, x1, h01, l01);
            split2(x2, x3, h23, l23);
            const uint32_t sw = swz((uint32_t)(row * 128 + (c0 + 4 * j) * 2));
            sts64(AH + sw, h01, h23);
            sts64(AL + sw, l01, l23);
        }
        const __nv_bfloat16* ph = g_W4t_hi + row * 128 + kc * 64 + c0;
        const __nv_bfloat16* pl = g_W4t_lo + row * 128 + kc * 64 + c0;
#pragma unroll
        for (int j = 0; j < 4; ++j) {
            const uint4 vh = *(const uint4*)(ph + 8 * j);
            const uint4 vl = *(const uint4*)(pl + 8 * j);
            const uint32_t sw = swz((uint32_t)(row * 128 + (c0 + 8 * j) * 2));
            sts128(BH + sw, vh);
            sts128(BL + sw, vl);
        }
        __syncthreads();
        mma_chunk(AH, AL, BH, BL, rowApart, kA, maskA, rowBpart, kB, maskB, acc);
    }
    __syncthreads();
    TC_STAGE();
    __syncthreads();

    const int r = t >> 1, ch = (t & 1) * 64;
    const int orow = r0 + r;
    const int rv = (orow < NN) ? orow : (NN - 1);
    const float* hp = &h[(size_t)rv * 128 + ch];

    float s = 0.f, q = 0.f;
#pragma unroll
    for (int qq = 0; qq < 16; ++qq) {
        float4 v = lds128(base + (uint32_t)(r * SS + ch + 4 * qq) * 4);
        const float4 hv = *(const float4*)(hp + 4 * qq);
        v.x += sB[ch + 4 * qq]     + hv.x;
        v.y += sB[ch + 4 * qq + 1] + hv.y;
        v.z += sB[ch + 4 * qq + 2] + hv.z;
        v.w += sB[ch + 4 * qq + 3] + hv.w;
        s += v.x + v.y + v.z + v.w;
        q += v.x * v.x + v.y * v.y + v.z * v.z + v.w * v.w;
    }
    s += __shfl_xor_sync(0xffffffffu, s, 1);
    q += __shfl_xor_sync(0xffffffffu, q, 1);
    const float mean = s * (1.0f / 128.0f);
    const float var  = fmaf(-mean, mean, q * (1.0f / 128.0f));
    const float inv  = rsqrtf(fmaxf(var, 0.f) + EPSV);

    if (orow < NN) {
        float* po = &out[(size_t)orow * 128 + ch];
#pragma unroll
        for (int qq = 0; qq < 16; ++qq) {
            float4 v = lds128(base + (uint32_t)(r * SS + ch + 4 * qq) * 4);
            const float4 hv = *(const float4*)(hp + 4 * qq);
            const int cb = ch + 4 * qq;
            const float z0 = v.x + sB[cb]     + hv.x;
            const float z1 = v.y + sB[cb + 1] + hv.y;
            const float z2 = v.z + sB[cb + 2] + hv.z;
            const float z3 = v.w + sB[cb + 3] + hv.w;
            *(float4*)(po + 4 * qq) = make_float4(
                (z0 - mean) * inv * sG[cb]     + sLb[cb],
                (z1 - mean) * inv * sG[cb + 1] + sLb[cb + 1],
                (z2 - mean) * inv * sG[cb + 2] + sLb[cb + 2],
                (z3 - mean) * inv * sG[cb + 3] + sLb[cb + 3]);
        }
    }
}

// ---------------- launch ----------------
extern "C" void kernel_launch(void* const* d_in, const int* in_sizes, int n_in,
                              void* d_out, int out_size) {
    const float* h   = (const float*)d_in[0];
    const float* ea  = (const float*)d_in[1];
    const float* W1  = (const float*)d_in[2];
    const float* b1  = (const float*)d_in[3];
    const float* g1  = (const float*)d_in[4];
    const float* be1 = (const float*)d_in[5];
    const float* W2  = (const float*)d_in[6];
    const float* b2  = (const float*)d_in[7];
    const float* W3  = (const float*)d_in[8];
    const float* b3  = (const float*)d_in[9];
    const float* g2  = (const float*)d_in[10];
    const float* be2 = (const float*)d_in[11];
    const float* W4  = (const float*)d_in[12];
    const float* b4  = (const float*)d_in[13];
    const float* lng = (const float*)d_in[14];
    const float* lnb = (const float*)d_in[15];
    const int*   ei  = (const int*)d_in[16];
    const int* src = ei;
    const int* dst = ei + NE;
    float* out = (float*)d_out;

    static bool attr_done = false;
    if (!attr_done) {
        cudaFuncSetAttribute(k_pq,       cudaFuncAttributeMaxDynamicSharedMemorySize, DSMEM_BYTES);
        cudaFuncSetAttribute(k_edge1,    cudaFuncAttributeMaxDynamicSharedMemorySize, DSMEM_BYTES);
        cudaFuncSetAttribute(k_gemm2_tc, cudaFuncAttributeMaxDynamicSharedMemorySize, DSMEM_GEMM2);
        cudaFuncSetAttribute(k_gemm3_tc, cudaFuncAttributeMaxDynamicSharedMemorySize, DSMEM_BYTES);
        cudaFuncSetAttribute(k_final_tc, cudaFuncAttributeMaxDynamicSharedMemorySize, DSMEM_BYTES);
        attr_done = true;
    }

    const int nb = (NN + 127) / 128;  // 391

    k_prep<<<160, 256>>>(W1, W2, W3, W4);
    k_pq<<<dim3(nb, 2), 256, DSMEM_BYTES>>>(h);
    k_edge1<<<NE / 128, 256, DSMEM_BYTES>>>(ea, b1, src, dst);
    k_gemm2_tc<<<NE / 128, 256, DSMEM_GEMM2>>>(b2, dst, g1, be1);
    k_gemm3_tc<<<nb, 256, DSMEM_BYTES>>>(h, b3);
    k_final_tc<<<nb, 256, DSMEM_BYTES>>>(h, b4, lng, lnb, g2, be2, out);
}

// round 16
// speedup vs baseline: 1.1217x; 1.1217x over previous
#include <cuda_runtime.h>
#include <cuda_bf16.h>
#include <cstdint>

#define NN   50000
#define NE   640000
#define EPSV 1e-5f

// ---------------- scratch (device globals; no allocation at launch) ----------------
__device__ __align__(128) __nv_bfloat16 g_xh[(size_t)NE * 128];  // BN1 input (bias added), bf16
__device__ __align__(128) float g_y[(size_t)NN * 128];     // BN2 input
__device__ __align__(128) float g_agg[(size_t)NN * 128];   // scatter-sum target
__device__ __align__(128) float g_P[(size_t)NN * 128];     // h @ W1a
__device__ __align__(128) float g_Q[(size_t)NN * 128];     // h @ W1b
__device__ __align__(128) float g_s1[128], g_q1[128], g_s2[128], g_q2[128];
__device__ __align__(128) float g_a1[128], g_c1[128], g_a2[128], g_c2[128];
// transposed + hi/lo-split weights ([N, K] K-contiguous)
__device__ __align__(128) __nv_bfloat16 g_Wa_hi[128 * 128],  g_Wa_lo[128 * 128];
__device__ __align__(128) __nv_bfloat16 g_Wb_hi[128 * 128],  g_Wb_lo[128 * 128];
__device__ __align__(128) __nv_bfloat16 g_Wc_hi[128 * 64],   g_Wc_lo[128 * 64];
__device__ __align__(128) __nv_bfloat16 g_W2t_hi[128 * 128], g_W2t_lo[128 * 128];
__device__ __align__(128) __nv_bfloat16 g_W3t_hi[128 * 256], g_W3t_lo[128 * 256];
__device__ __align__(128) __nv_bfloat16 g_W4t_hi[128 * 128], g_W4t_lo[128 * 128];

// ---------------- small helpers ----------------
__device__ __forceinline__ uint32_t smem_u32(const void* p) {
    return (uint32_t)__cvta_generic_to_shared(p);
}
__device__ __forceinline__ uint32_t swz(uint32_t o) { return o ^ ((o >> 3) & 0x70); }
__device__ __forceinline__ void sts64(uint32_t a, uint32_t x, uint32_t y) {
    asm volatile("st.shared.v2.b32 [%0], {%1,%2};" :: "r"(a), "r"(x), "r"(y));
}
__device__ __forceinline__ void sts128(uint32_t a, uint4 v) {
    asm volatile("st.shared.v4.b32 [%0], {%1,%2,%3,%4};" :: "r"(a), "r"(v.x), "r"(v.y), "r"(v.z), "r"(v.w));
}
__device__ __forceinline__ void sts64f(uint32_t a, float x, float y) {
    asm volatile("st.shared.v2.f32 [%0], {%1,%2};" :: "r"(a), "f"(x), "f"(y));
}
__device__ __forceinline__ void sts128f(uint32_t a, float x, float y, float z, float w) {
    asm volatile("st.shared.v4.f32 [%0], {%1,%2,%3,%4};" :: "r"(a), "f"(x), "f"(y), "f"(z), "f"(w));
}
__device__ __forceinline__ float lds32(uint32_t a) {
    float v; asm volatile("ld.shared.f32 %0, [%1];" : "=f"(v) : "r"(a)); return v;
}
__device__ __forceinline__ float4 lds128(uint32_t a) {
    float4 v;
    asm volatile("ld.shared.v4.f32 {%0,%1,%2,%3}, [%4];"
                 : "=f"(v.x), "=f"(v.y), "=f"(v.z), "=f"(v.w) : "r"(a));
    return v;
}
__device__ __forceinline__ uint4 lds128u(uint32_t a) {
    uint4 v;
    asm volatile("ld.shared.v4.b32 {%0,%1,%2,%3}, [%4];"
                 : "=r"(v.x), "=r"(v.y), "=r"(v.z), "=r"(v.w) : "r"(a));
    return v;
}
__device__ __forceinline__ void cpasync16(uint32_t dst, const void* src) {
    asm volatile("cp.async.ca.shared.global [%0], [%1], 16;" :: "r"(dst), "l"(src));
}
__device__ __forceinline__ uint32_t pkbf(__nv_bfloat16 a, __nv_bfloat16 b) {
    __nv_bfloat162 t(a, b);
    return *reinterpret_cast<uint32_t*>(&t);
}
__device__ __forceinline__ void split2(float a, float b, uint32_t& hh, uint32_t& ll) {
    __nv_bfloat16 ha = __float2bfloat16_rn(a), hb = __float2bfloat16_rn(b);
    float la = a - __bfloat162float(ha), lb = b - __bfloat162float(hb);
    hh = pkbf(ha, hb);
    ll = pkbf(__float2bfloat16_rn(la), __float2bfloat16_rn(lb));
}
__device__ __forceinline__ void red4(float* p, float a, float b, float c, float d) {
    asm volatile("red.global.add.v4.f32 [%0], {%1, %2, %3, %4};"
                 :: "l"(p), "f"(a), "f"(b), "f"(c), "f"(d) : "memory");
}
__device__ __forceinline__ void red2(float* p, float a, float b) {
    asm volatile("red.global.add.v2.f32 [%0], {%1, %2};"
                 :: "l"(p), "f"(a), "f"(b) : "memory");
}

// ---------------- tensor-core primitives ----------------
__device__ __forceinline__ void mma16816(float* c, const uint32_t* a, uint32_t b0, uint32_t b1) {
    asm volatile("mma.sync.aligned.m16n8k16.row.col.f32.bf16.bf16.f32 "
        "{%0,%1,%2,%3}, {%4,%5,%6,%7}, {%8,%9}, {%0,%1,%2,%3};"
        : "+f"(c[0]), "+f"(c[1]), "+f"(c[2]), "+f"(c[3])
        : "r"(a[0]), "r"(a[1]), "r"(a[2]), "r"(a[3]), "r"(b0), "r"(b1));
}
__device__ __forceinline__ void ldsm4(uint32_t* r, uint32_t addr) {
    asm volatile("ldmatrix.sync.aligned.m8n8.x4.shared.b16 {%0,%1,%2,%3}, [%4];"
        : "=r"(r[0]), "=r"(r[1]), "=r"(r[2]), "=r"(r[3]) : "r"(addr));
}

// One 64-deep K chunk: 4 k16-steps, warp tile 32(M)x64(N), 3-term hi/lo split.
__device__ __forceinline__ void mma_chunk(
    uint32_t AH, uint32_t AL, uint32_t BH, uint32_t BL,
    uint32_t rowApart, uint32_t kA, uint32_t maskA,
    uint32_t rowBpart, uint32_t kB, uint32_t maskB,
    float (&acc)[2][4][2][4])
{
#pragma unroll
    for (int s = 0; s < 4; ++s) {
        const uint32_t offA = (kA + s * 32) ^ maskA;
        const uint32_t offB = (kB + s * 32) ^ maskB;
        uint32_t ah[2][4], al[2][4];
#pragma unroll
        for (int i = 0; i < 2; ++i) {
            ldsm4(ah[i], AH + rowApart + i * 2048 + offA);
            ldsm4(al[i], AL + rowApart + i * 2048 + offA);
        }
#pragma unroll
        for (int j = 0; j < 4; ++j) {
            uint32_t bh[4], bl[4];
            ldsm4(bh, BH + rowBpart + j * 2048 + offB);
            ldsm4(bl, BL + rowBpart + j * 2048 + offB);
#pragma unroll
            for (int i = 0; i < 2; ++i) {
#pragma unroll
                for (int hh = 0; hh < 2; ++hh) {
                    mma16816(acc[i][j][hh], ah[i], bh[hh * 2], bh[hh * 2 + 1]);
                    mma16816(acc[i][j][hh], ah[i], bl[hh * 2], bl[hh * 2 + 1]);
                    mma16816(acc[i][j][hh], al[i], bh[hh * 2], bh[hh * 2 + 1]);
                }
            }
        }
    }
}

#define SS 132
#define DSMEM_BYTES (1024 + 128 * SS * 4)                 // 4-tile kernels with stage
#define DSMEM_GEMM2 (1024 + 4 * 16384 + 128 * 144)        // 4 tiles + 18KB chunk-1 prefetch

// warp/lane geometry + accumulator init
#define TC_GEOM()                                                                  \
    const int w = t >> 5, l = t & 31;                                              \
    const int mw = (w >> 1) * 32, nw = (w & 1) * 64;                               \
    const uint32_t rowApart = (uint32_t)(mw + (l & 15)) * 128;                     \
    const uint32_t kA = (uint32_t)(l >> 4) * 16;                                   \
    const uint32_t maskA = (uint32_t)(l & 7) << 4;                                 \
    const uint32_t rowBpart = (uint32_t)(nw + (l & 7) + ((l >> 4) << 3)) * 128;    \
    const uint32_t kB = (uint32_t)((l >> 3) & 1) * 16;                             \
    const uint32_t maskB = maskA;                                                  \
    float acc[2][4][2][4];                                                         \
    _Pragma("unroll") for (int i = 0; i < 2; ++i)                                  \
    _Pragma("unroll") for (int j = 0; j < 4; ++j)                                  \
    _Pragma("unroll") for (int hh = 0; hh < 2; ++hh)                               \
    _Pragma("unroll") for (int q = 0; q < 4; ++q) acc[i][j][hh][q] = 0.f;

#define TC_TILES()                                                                 \
    const uint32_t base = (smem_u32(dsm) + 1023) & ~1023u;                         \
    const uint32_t AH = base, AL = base + 16384, BH = base + 32768, BL = base + 49152;

#define TC_STAGE()                                                                 \
    _Pragma("unroll") for (int i = 0; i < 2; ++i)                                  \
    _Pragma("unroll") for (int j = 0; j < 4; ++j)                                  \
    _Pragma("unroll") for (int hh = 0; hh < 2; ++hh) {                             \
        const int col  = nw + j * 16 + hh * 8 + 2 * (l & 3);                       \
        const int row0 = mw + i * 16 + (l >> 2);                                   \
        sts64f(base + (uint32_t)(row0 * SS + col) * 4,       acc[i][j][hh][0], acc[i][j][hh][1]); \
        sts64f(base + (uint32_t)((row0 + 8) * SS + col) * 4, acc[i][j][hh][2], acc[i][j][hh][3]); \
    }

// ---------------- kernel: zero agg + stats ----------------
__global__ void k_zero() {
    const size_t tot = (size_t)NN * 128;
    const size_t stride = (size_t)gridDim.x * blockDim.x;
    for (size_t k = (size_t)blockIdx.x * blockDim.x + threadIdx.x; k < tot; k += stride)
        g_agg[k] = 0.f;
    if (blockIdx.x == 0 && threadIdx.x < 128) {
        g_s1[threadIdx.x] = 0.f; g_q1[threadIdx.x] = 0.f;
        g_s2[threadIdx.x] = 0.f; g_q2[threadIdx.x] = 0.f;
    }
}

// ---------------- kernel: transpose + hi/lo split all weights ----------------
__global__ void k_prep(const float* __restrict__ W1, const float* __restrict__ W2,
                       const float* __restrict__ W3, const float* __restrict__ W4) {
    const int stride = gridDim.x * blockDim.x;
    const int t0 = blockIdx.x * blockDim.x + threadIdx.x;
    for (int idx = t0; idx < 128 * 128; idx += stride) {
        const int n = idx >> 7, k = idx & 127;
        float v = W1[k * 128 + n];
        __nv_bfloat16 hv = __float2bfloat16_rn(v);
        g_Wa_hi[idx] = hv; g_Wa_lo[idx] = __float2bfloat16_rn(v - __bfloat162float(hv));
        v = W1[(128 + k) * 128 + n];
        hv = __float2bfloat16_rn(v);
        g_Wb_hi[idx] = hv; g_Wb_lo[idx] = __float2bfloat16_rn(v - __bfloat162float(hv));
        v = W2[k * 128 + n];
        hv = __float2bfloat16_rn(v);
        g_W2t_hi[idx] = hv; g_W2t_lo[idx] = __float2bfloat16_rn(v - __bfloat162float(hv));
        v = W4[k * 128 + n];
        hv = __float2bfloat16_rn(v);
        g_W4t_hi[idx] = hv; g_W4t_lo[idx] = __float2bfloat16_rn(v - __bfloat162float(hv));
    }
    for (int idx = t0; idx < 128 * 64; idx += stride) {
        const int n = idx >> 6, k = idx & 63;
        const float v = W1[(256 + k) * 128 + n];
        const __nv_bfloat16 hv = __float2bfloat16_rn(v);
        g_Wc_hi[idx] = hv; g_Wc_lo[idx] = __float2bfloat16_rn(v - __bfloat162float(hv));
    }
    for (int idx = t0; idx < 128 * 256; idx += stride) {
        const int n = idx >> 8, k = idx & 255;
        const float v = W3[k * 128 + n];
        const __nv_bfloat16 hv = __float2bfloat16_rn(v);
        g_W3t_hi[idx] = hv; g_W3t_lo[idx] = __float2bfloat16_rn(v - __bfloat162float(hv));
    }
}

// ---------------- k_pq: P = h @ W1a, Q = h @ W1b (node GEMMs) ----------------
__global__ __launch_bounds__(256, 2) void k_pq(const float* __restrict__ h) {
    extern __shared__ __align__(16) char dsm[];
    const int t = threadIdx.x;
    const int r0 = blockIdx.x * 128;
    const int sel = blockIdx.y;

    TC_TILES();
    TC_GEOM();

    const __nv_bfloat16* WH = sel ? g_Wb_hi : g_Wa_hi;
    const __nv_bfloat16* WL = sel ? g_Wb_lo : g_Wa_lo;

    const int row = t >> 1, c0 = (t & 1) * 32;
    int rg = r0 + row; if (rg >= NN) rg = NN - 1;

    for (int kc = 0; kc < 2; ++kc) {
        __syncthreads();
        const float* ap = h + (size_t)rg * 128 + kc * 64 + c0;
#pragma unroll
        for (int j = 0; j < 8; ++j) {
            const float4 f = *(const float4*)(ap + 4 * j);
            uint32_t h01, l01, h23, l23;
            split2(f.x, f.y, h01, l01);
            split2(f.z, f.w, h23, l23);
            const uint32_t sw = swz((uint32_t)(row * 128 + (c0 + 4 * j) * 2));
            sts64(AH + sw, h01, h23);
            sts64(AL + sw, l01, l23);
        }
        const __nv_bfloat16* ph = WH + row * 128 + kc * 64 + c0;
        const __nv_bfloat16* pl = WL + row * 128 + kc * 64 + c0;
#pragma unroll
        for (int j = 0; j < 4; ++j) {
            const uint4 vh = *(const uint4*)(ph + 8 * j);
            const uint4 vl = *(const uint4*)(pl + 8 * j);
            const uint32_t sw = swz((uint32_t)(row * 128 + (c0 + 8 * j) * 2));
            sts128(BH + sw, vh);
            sts128(BL + sw, vl);
        }
        __syncthreads();
        mma_chunk(AH, AL, BH, BL, rowApart, kA, maskA, rowBpart, kB, maskB, acc);
    }
    __syncthreads();
    TC_STAGE();
    __syncthreads();

    const int r = t >> 1, ch = (t & 1) * 64;
    const int orow = r0 + r;
    if (orow < NN) {
        float* po = (sel ? g_Q : g_P) + (size_t)orow * 128 + ch;
#pragma unroll
        for (int q = 0; q < 16; ++q)
            *(float4*)(po + 4 * q) = lds128(base + (uint32_t)(r * SS + ch + 4 * q) * 4);
    }
}

// ---------------- k_edge1: x = ea@Wc + P[src] + Q[dst] + b1 -> g_xh(bf16) ; column stats ----------------
__global__ __launch_bounds__(256, 2) void k_edge1(
    const float* __restrict__ ea, const float* __restrict__ b1,
    const int* __restrict__ src, const int* __restrict__ dst)
{
    extern __shared__ __align__(16) char dsm[];
    __shared__ int sSoff[128], sDoff[128];
    __shared__ float sB[128];

    const int t = threadIdx.x;
    const int e0 = blockIdx.x * 128;

    TC_TILES();
    TC_GEOM();

    if (t < 128) { sSoff[t] = src[e0 + t] * 128; sB[t] = b1[t]; }
    else         sDoff[t - 128] = dst[e0 + t - 128] * 128;

    const int row = t >> 1, c0 = (t & 1) * 32;

    // single K=64 chunk: A = ea rows, B = W1c
    {
        const float* ap = ea + (size_t)(e0 + row) * 64 + c0;
#pragma unroll
        for (int j = 0; j < 8; ++j) {
            const float4 f = *(const float4*)(ap + 4 * j);
            uint32_t h01, l01, h23, l23;
            split2(f.x, f.y, h01, l01);
            split2(f.z, f.w, h23, l23);
            const uint32_t sw = swz((uint32_t)(row * 128 + (c0 + 4 * j) * 2));
            sts64(AH + sw, h01, h23);
            sts64(AL + sw, l01, l23);
        }
        const __nv_bfloat16* ph = g_Wc_hi + row * 64 + c0;
        const __nv_bfloat16* pl = g_Wc_lo + row * 64 + c0;
#pragma unroll
        for (int j = 0; j < 4; ++j) {
            const uint4 vh = *(const uint4*)(ph + 8 * j);
            const uint4 vl = *(const uint4*)(pl + 8 * j);
            const uint32_t sw = swz((uint32_t)(row * 128 + (c0 + 8 * j) * 2));
            sts128(BH + sw, vh);
            sts128(BL + sw, vl);
        }
        __syncthreads();
        mma_chunk(AH, AL, BH, BL, rowApart, kA, maskA, rowBpart, kB, maskB, acc);
    }
    __syncthreads();
    TC_STAGE();
    __syncthreads();

    // add gathered P/Q + bias; write g_xh (bf16); write fp32 x back into stage for stats
#pragma unroll
    for (int pass = 0; pass < 4; ++pass) {
        const int r = pass * 32 + (t >> 3);
        const float* pP = g_P + sSoff[r];
        const float* pQ = g_Q + sDoff[r];
        __nv_bfloat16* gx = g_xh + (size_t)(e0 + r) * 128;
#pragma unroll
        for (int q = 0; q < 4; ++q) {
            const int col = (t & 7) * 4 + 32 * q;
            const uint32_t sa = base + (uint32_t)(r * SS + col) * 4;
            float4 v = lds128(sa);
            const float4 p4 = *(const float4*)(pP + col);
            const float4 q4 = *(const float4*)(pQ + col);
            v.x += p4.x + q4.x + sB[col];
            v.y += p4.y + q4.y + sB[col + 1];
            v.z += p4.z + q4.z + sB[col + 2];
            v.w += p4.w + q4.w + sB[col + 3];
            uint2 pk;
            pk.x = pkbf(__float2bfloat16_rn(v.x), __float2bfloat16_rn(v.y));
            pk.y = pkbf(__float2bfloat16_rn(v.z), __float2bfloat16_rn(v.w));
            *(uint2*)(gx + col) = pk;
            sts128f(sa, v.x, v.y, v.z, v.w);
        }
    }
    __syncthreads();
    // column stats: all 256 threads, each covers 64 rows of one column
    {
        const int col = t & 127, half = t >> 7;
        float s = 0.f, q = 0.f;
#pragma unroll 8
        for (int rr = half * 64; rr < half * 64 + 64; ++rr) {
            const float v = lds32(base + (uint32_t)(rr * SS + col) * 4);
            s += v; q += v * v;
        }
        atomicAdd(&g_s1[col], s);
        atomicAdd(&g_q1[col], q);
    }
}

// ---------------- fold BN stats ----------------
__global__ void k_bn1(const float* __restrict__ g, const float* __restrict__ be) {
    const int t = threadIdx.x;
    const float m   = g_s1[t] * (1.0f / (float)NE);
    const float var = fmaf(-m, m, g_q1[t] * (1.0f / (float)NE));
    const float a   = g[t] * rsqrtf(fmaxf(var, 0.f) + EPSV);
    g_a1[t] = a;
    g_c1[t] = fmaf(-m, a, be[t]);
}
__global__ void k_bn2(const float* __restrict__ g, const float* __restrict__ be) {
    const int t = threadIdx.x;
    const float m   = g_s2[t] * (1.0f / (float)NN);
    const float var = fmaf(-m, m, g_q2[t] * (1.0f / (float)NN));
    const float a   = g[t] * rsqrtf(fmaxf(var, 0.f) + EPSV);
    g_a2[t] = a;
    g_c2[t] = fmaf(-m, a, be[t]);
}

// ---------------- k_gemm2: messages = relu(BN(g_xh)) @ W2 + b2 ; direct fragment scatter ----------------
__global__ __launch_bounds__(256, 2) void k_gemm2_tc(
    const float* __restrict__ b2, const int* __restrict__ dst)
{
    extern __shared__ __align__(16) char dsm[];
    __shared__ int sDoff[128];
    __shared__ float sB[128], sA[128], sC[128];

    const int t = threadIdx.x;
    const int e0 = blockIdx.x * 128;

    TC_TILES();
    const uint32_t Xb = base + 65536;   // 128 rows x 144B prefetch buffer for chunk 1
    TC_GEOM();

    const int row = t >> 1, c0 = (t & 1) * 32;

    // prefetch chunk-1 A data (bf16, 64B per thread) while chunk 0 runs
    {
        const char* srcp = (const char*)(g_xh + (size_t)(e0 + row) * 128 + 64) + (t & 1) * 64;
        const uint32_t dstp = Xb + (uint32_t)row * 144 + (t & 1) * 64;
#pragma unroll
        for (int j = 0; j < 4; ++j) cpasync16(dstp + 16 * j, srcp + 16 * j);
        asm volatile("cp.async.commit_group;");
    }

    if (t < 128) {
        sDoff[t] = dst[e0 + t] * 128;
        sB[t] = b2[t]; sA[t] = g_a1[t]; sC[t] = g_c1[t];
    }

    for (int kc = 0; kc < 2; ++kc) {
        __syncthreads();
        if (kc == 1) asm volatile("cp.async.wait_group 0;" ::: "memory");
#pragma unroll
        for (int j = 0; j < 4; ++j) {
            uint4 u;
            if (kc == 0) u = *(const uint4*)(g_xh + (size_t)(e0 + row) * 128 + c0 + 8 * j);
            else         u = lds128u(Xb + (uint32_t)row * 144 + (c0 + 8 * j) * 2);
            const int cc = kc * 64 + c0 + 8 * j;
            uint32_t hv[4], lv[4];
            {
                const float2 f = __bfloat1622float2(*reinterpret_cast<__nv_bfloat162*>(&u.x));
                const float r0 = fmaxf(fmaf(sA[cc],     f.x, sC[cc]),     0.f);
                const float r1 = fmaxf(fmaf(sA[cc + 1], f.y, sC[cc + 1]), 0.f);
                split2(r0, r1, hv[0], lv[0]);
            }
            {
                const float2 f = __bfloat1622float2(*reinterpret_cast<__nv_bfloat162*>(&u.y));
                const float r0 = fmaxf(fmaf(sA[cc + 2], f.x, sC[cc + 2]), 0.f);
                const float r1 = fmaxf(fmaf(sA[cc + 3], f.y, sC[cc + 3]), 0.f);
                split2(r0, r1, hv[1], lv[1]);
            }
            {
                const float2 f = __bfloat1622float2(*reinterpret_cast<__nv_bfloat162*>(&u.z));
                const float r0 = fmaxf(fmaf(sA[cc + 4], f.x, sC[cc + 4]), 0.f);
                const float r1 = fmaxf(fmaf(sA[cc + 5], f.y, sC[cc + 5]), 0.f);
                split2(r0, r1, hv[2], lv[2]);
            }
            {
                const float2 f = __bfloat1622float2(*reinterpret_cast<__nv_bfloat162*>(&u.w));
                const float r0 = fmaxf(fmaf(sA[cc + 6], f.x, sC[cc + 6]), 0.f);
                const float r1 = fmaxf(fmaf(sA[cc + 7], f.y, sC[cc + 7]), 0.f);
                split2(r0, r1, hv[3], lv[3]);
            }
            const uint32_t sw = swz((uint32_t)(row * 128 + (c0 + 8 * j) * 2));
            sts128(AH + sw, make_uint4(hv[0], hv[1], hv[2], hv[3]));
            sts128(AL + sw, make_uint4(lv[0], lv[1], lv[2], lv[3]));
        }
        const __nv_bfloat16* ph = g_W2t_hi + row * 128 + kc * 64 + c0;
        const __nv_bfloat16* pl = g_W2t_lo + row * 128 + kc * 64 + c0;
#pragma unroll
        for (int j = 0; j < 4; ++j) {
            const uint4 vh = *(const uint4*)(ph + 8 * j);
            const uint4 vl = *(const uint4*)(pl + 8 * j);
            const uint32_t sw = swz((uint32_t)(row * 128 + (c0 + 8 * j) * 2));
            sts128(BH + sw, vh);
            sts128(BL + sw, vl);
        }
        __syncthreads();
        mma_chunk(AH, AL, BH, BL, rowApart, kA, maskA, rowBpart, kB, maskB, acc);
    }

    // direct fragment scatter: no stage, no extra syncs
#pragma unroll
    for (int i = 0; i < 2; ++i) {
#pragma unroll
        for (int q2 = 0; q2 < 2; ++q2) {
            const int r = mw + i * 16 + (l >> 2) + q2 * 8;
            const int doff = sDoff[r];
#pragma unroll
            for (int j = 0; j < 4; ++j) {
#pragma unroll
                for (int hh = 0; hh < 2; ++hh) {
                    const int c = nw + j * 16 + hh * 8 + 2 * (l & 3);
                    red2(&g_agg[(size_t)doff + c],
                         acc[i][j][hh][2 * q2 + 0] + sB[c],
                         acc[i][j][hh][2 * q2 + 1] + sB[c + 1]);
                }
            }
        }
    }
}

// ---------------- k_gemm3: y = [h|agg] @ W3 + b3 ; column stats ----------------
__global__ __launch_bounds__(256, 2) void k_gemm3_tc(
    const float* __restrict__ h, const float* __restrict__ b3)
{
    extern __shared__ __align__(16) char dsm[];
    __shared__ float sB[128];

    const int t = threadIdx.x;
    const int r0 = blockIdx.x * 128;

    TC_TILES();
    TC_GEOM();

    if (t < 128) sB[t] = b3[t];

    const int row = t >> 1, c0 = (t & 1) * 32;
    int rg = r0 + row; if (rg >= NN) rg = NN - 1;

    for (int kc = 0; kc < 4; ++kc) {
        __syncthreads();
        const int kg = kc * 64 + c0;
        const float* ap = (kg < 128) ? (h + (size_t)rg * 128 + kg)
                                     : (&g_agg[(size_t)rg * 128 + (kg - 128)]);
#pragma unroll
        for (int j = 0; j < 8; ++j) {
            const float4 f = *(const float4*)(ap + 4 * j);
            uint32_t h01, l01, h23, l23;
            split2(f.x, f.y, h01, l01);
            split2(f.z, f.w, h23, l23);
            const uint32_t sw = swz((uint32_t)(row * 128 + (c0 + 4 * j) * 2));
            sts64(AH + sw, h01, h23);
            sts64(AL + sw, l01, l23);
        }
        const __nv_bfloat16* ph = g_W3t_hi + row * 256 + kc * 64 + c0;
        const __nv_bfloat16* pl = g_W3t_lo + row * 256 + kc * 64 + c0;
#pragma unroll
        for (int j = 0; j < 4; ++j) {
            const uint4 vh = *(const uint4*)(ph + 8 * j);
            const uint4 vl = *(const uint4*)(pl + 8 * j);
            const uint32_t sw = swz((uint32_t)(row * 128 + (c0 + 8 * j) * 2));
            sts128(BH + sw, vh);
            sts128(BL + sw, vl);
        }
        __syncthreads();
        mma_chunk(AH, AL, BH, BL, rowApart, kA, maskA, rowBpart, kB, maskB, acc);
    }
    __syncthreads();
    TC_STAGE();
    __syncthreads();

    const int r = t >> 1, ch = (t & 1) * 64;
    const int orow = r0 + r;
    if (orow < NN) {
        float* gy = &g_y[(size_t)orow * 128 + ch];
#pragma unroll
        for (int q = 0; q < 16; ++q) {
            float4 v = lds128(base + (uint32_t)(r * SS + ch + 4 * q) * 4);
            v.x += sB[ch + 4 * q];
            v.y += sB[ch + 4 * q + 1];
            v.z += sB[ch + 4 * q + 2];
            v.w += sB[ch + 4 * q + 3];
            *(float4*)(gy + 4 * q) = v;
        }
    }
    {
        int lim = NN - r0; if (lim > 128) lim = 128;
        const int col = t & 127, half = t >> 7;
        const float bias = sB[col];
        float s = 0.f, q = 0.f;
        const int rend = min(half * 64 + 64, lim);
        for (int rr = half * 64; rr < rend; ++rr) {
            const float v = lds32(base + (uint32_t)(rr * SS + col) * 4) + bias;
            s += v; q += v * v;
        }
        atomicAdd(&g_s2[col], s);
        atomicAdd(&g_q2[col], q);
    }
}

// ---------------- k_final: h_new = relu(BN(y)) @ W4 + b4 ; residual + LayerNorm ----------------
__global__ __launch_bounds__(256, 2) void k_final_tc(
    const float* __restrict__ h, const float* __restrict__ b4,
    const float* __restrict__ lng, const float* __restrict__ lnb, float* __restrict__ out)
{
    extern __shared__ __align__(16) char dsm[];
    __shared__ float sB[128], sA[128], sC[128], sG[128], sLb[128];

    const int t = threadIdx.x;
    const int r0 = blockIdx.x * 128;

    TC_TILES();
    TC_GEOM();

    if (t < 128) {
        sB[t] = b4[t]; sA[t] = g_a2[t]; sC[t] = g_c2[t];
        sG[t] = lng[t]; sLb[t] = lnb[t];
    }

    const int row = t >> 1, c0 = (t & 1) * 32;
    int rg = r0 + row; if (rg >= NN) rg = NN - 1;

    for (int kc = 0; kc < 2; ++kc) {
        __syncthreads();
        const float* ap = g_y + (size_t)rg * 128 + kc * 64 + c0;
#pragma unroll
        for (int j = 0; j < 8; ++j) {
            const float4 f = *(const float4*)(ap + 4 * j);
            const int col = kc * 64 + c0 + 4 * j;
            const float x0 = fmaxf(fmaf(sA[col],     f.x, sC[col]),     0.f);
            const float x1 = fmaxf(fmaf(sA[col + 1], f.y, sC[col + 1]), 0.f);
            const float x2 = fmaxf(fmaf(sA[col + 2], f.z, sC[col + 2]), 0.f);
            const float x3 = fmaxf(fmaf(sA[col + 3], f.w, sC[col + 3]), 0.f);
            uint32_t h01, l01, h23, l23;
            split2(x0, x1, h01, l01);
            split2(x2, x3, h23, l23);
            const uint32_t sw = swz((uint32_t)(row * 128 + (c0 + 4 * j) * 2));
            sts64(AH + sw, h01, h23);
            sts64(AL + sw, l01, l23);
        }
        const __nv_bfloat16* ph = g_W4t_hi + row * 128 + kc * 64 + c0;
        const __nv_bfloat16* pl = g_W4t_lo + row * 128 + kc * 64 + c0;
#pragma unroll
        for (int j = 0; j < 4; ++j) {
            const uint4 vh = *(const uint4*)(ph + 8 * j);
            const uint4 vl = *(const uint4*)(pl + 8 * j);
            const uint32_t sw = swz((uint32_t)(row * 128 + (c0 + 8 * j) * 2));
            sts128(BH + sw, vh);
            sts128(BL + sw, vl);
        }
        __syncthreads();
        mma_chunk(AH, AL, BH, BL, rowApart, kA, maskA, rowBpart, kB, maskB, acc);
    }
    __syncthreads();
    TC_STAGE();
    __syncthreads();

    const int r = t >> 1, ch = (t & 1) * 64;
    const int orow = r0 + r;
    const int rv = (orow < NN) ? orow : (NN - 1);
    const float* hp = &h[(size_t)rv * 128 + ch];

    float s = 0.f, q = 0.f;
#pragma unroll
    for (int qq = 0; qq < 16; ++qq) {
        float4 v = lds128(base + (uint32_t)(r * SS + ch + 4 * qq) * 4);
        const float4 hv = *(const float4*)(hp + 4 * qq);
        v.x += sB[ch + 4 * qq]     + hv.x;
        v.y += sB[ch + 4 * qq + 1] + hv.y;
        v.z += sB[ch + 4 * qq + 2] + hv.z;
        v.w += sB[ch + 4 * qq + 3] + hv.w;
        s += v.x + v.y + v.z + v.w;
        q += v.x * v.x + v.y * v.y + v.z * v.z + v.w * v.w;
    }
    s += __shfl_xor_sync(0xffffffffu, s, 1);
    q += __shfl_xor_sync(0xffffffffu, q, 1);
    const float mean = s * (1.0f / 128.0f);
    const float var  = fmaf(-mean, mean, q * (1.0f / 128.0f));
    const float inv  = rsqrtf(fmaxf(var, 0.f) + EPSV);

    if (orow < NN) {
        float* po = &out[(size_t)orow * 128 + ch];
#pragma unroll
        for (int qq = 0; qq < 16; ++qq) {
            float4 v = lds128(base + (uint32_t)(r * SS + ch + 4 * qq) * 4);
            const float4 hv = *(const float4*)(hp + 4 * qq);
            const int cb = ch + 4 * qq;
            const float z0 = v.x + sB[cb]     + hv.x;
            const float z1 = v.y + sB[cb + 1] + hv.y;
            const float z2 = v.z + sB[cb + 2] + hv.z;
            const float z3 = v.w + sB[cb + 3] + hv.w;
            *(float4*)(po + 4 * qq) = make_float4(
                (z0 - mean) * inv * sG[cb]     + sLb[cb],
                (z1 - mean) * inv * sG[cb + 1] + sLb[cb + 1],
                (z2 - mean) * inv * sG[cb + 2] + sLb[cb + 2],
                (z3 - mean) * inv * sG[cb + 3] + sLb[cb + 3]);
        }
    }
}

// ---------------- launch ----------------
extern "C" void kernel_launch(void* const* d_in, const int* in_sizes, int n_in,
                              void* d_out, int out_size) {
    const float* h   = (const float*)d_in[0];
    const float* ea  = (const float*)d_in[1];
    const float* W1  = (const float*)d_in[2];
    const float* b1  = (const float*)d_in[3];
    const float* g1  = (const float*)d_in[4];
    const float* be1 = (const float*)d_in[5];
    const float* W2  = (const float*)d_in[6];
    const float* b2  = (const float*)d_in[7];
    const float* W3  = (const float*)d_in[8];
    const float* b3  = (const float*)d_in[9];
    const float* g2  = (const float*)d_in[10];
    const float* be2 = (const float*)d_in[11];
    const float* W4  = (const float*)d_in[12];
    const float* b4  = (const float*)d_in[13];
    const float* lng = (const float*)d_in[14];
    const float* lnb = (const float*)d_in[15];
    const int*   ei  = (const int*)d_in[16];
    const int* src = ei;
    const int* dst = ei + NE;
    float* out = (float*)d_out;

    static bool attr_done = false;
    if (!attr_done) {
        cudaFuncSetAttribute(k_pq,       cudaFuncAttributeMaxDynamicSharedMemorySize, DSMEM_BYTES);
        cudaFuncSetAttribute(k_edge1,    cudaFuncAttributeMaxDynamicSharedMemorySize, DSMEM_BYTES);
        cudaFuncSetAttribute(k_gemm2_tc, cudaFuncAttributeMaxDynamicSharedMemorySize, DSMEM_GEMM2);
        cudaFuncSetAttribute(k_gemm3_tc, cudaFuncAttributeMaxDynamicSharedMemorySize, DSMEM_BYTES);
        cudaFuncSetAttribute(k_final_tc, cudaFuncAttributeMaxDynamicSharedMemorySize, DSMEM_BYTES);
        attr_done = true;
    }

    const int nb = (NN + 127) / 128;  // 391

    k_zero<<<1024, 256>>>();
    k_prep<<<160, 256>>>(W1, W2, W3, W4);
    k_pq<<<dim3(nb, 2), 256, DSMEM_BYTES>>>(h);
    k_edge1<<<NE / 128, 256, DSMEM_BYTES>>>(ea, b1, src, dst);
    k_bn1<<<1, 128>>>(g1, be1);
    k_gemm2_tc<<<NE / 128, 256, DSMEM_GEMM2>>>(b2, dst);
    k_gemm3_tc<<<nb, 256, DSMEM_BYTES>>>(h, b3);
    k_bn2<<<1, 128>>>(g2, be2);
    k_final_tc<<<nb, 256, DSMEM_BYTES>>>(h, b4, lng, lnb, out);
}